// round 1
// baseline (speedup 1.0000x reference)
#include <cuda_runtime.h>
#include <cuda_bf16.h>
#include <cstdint>

// Problem constants
#define Bq   8
#define Lq   1024
#define Eq   512
#define Hq   8
#define HDq  64
#define Pq   2047          // 2*L-1
#define BLq  8192          // B*L
#define QKVq 1536          // 3*E

// Scratch (device globals; no allocations allowed)
__device__ float g_proj[(size_t)BLq * QKVq];      // (B*L, 3E)  qkv projection
__device__ float g_pk[(size_t)Pq * Eq];           // (P, E)     positional keys
__device__ float g_ctx[(size_t)BLq * Eq];         // (B*L, E)   context
__device__ float g_attn_fb[(size_t)Bq * Hq * Lq * Lq]; // fallback attn buffer

// ---------------------------------------------------------------------------
// Generic SGEMM: C[M,N] = A[M,K] @ W[N,K]^T (+bias). K % 16 == 0 required.
// 64x64 tile, BK=16, 256 threads, 4x4 per thread.
// ---------------------------------------------------------------------------
__global__ void gemm_nt(const float* __restrict__ A, const float* __restrict__ W,
                        const float* __restrict__ bias, float* __restrict__ C,
                        int M, int N, int K, int lda, int ldw, int ldc)
{
    __shared__ float As[16][65];
    __shared__ float Ws[16][65];

    const int m0 = blockIdx.y * 64;
    const int n0 = blockIdx.x * 64;
    const int t  = threadIdx.x;
    const int tx = t & 15, ty = t >> 4;

    const int lr = t >> 2;        // 0..63
    const int lc = (t & 3) * 4;   // 0,4,8,12

    float acc[4][4] = {};

    for (int k0 = 0; k0 < K; k0 += 16) {
        float4 av = make_float4(0.f, 0.f, 0.f, 0.f);
        if (m0 + lr < M)
            av = *(const float4*)(A + (size_t)(m0 + lr) * lda + k0 + lc);
        As[lc + 0][lr] = av.x; As[lc + 1][lr] = av.y;
        As[lc + 2][lr] = av.z; As[lc + 3][lr] = av.w;

        float4 wv = make_float4(0.f, 0.f, 0.f, 0.f);
        if (n0 + lr < N)
            wv = *(const float4*)(W + (size_t)(n0 + lr) * ldw + k0 + lc);
        Ws[lc + 0][lr] = wv.x; Ws[lc + 1][lr] = wv.y;
        Ws[lc + 2][lr] = wv.z; Ws[lc + 3][lr] = wv.w;

        __syncthreads();
        #pragma unroll
        for (int kk = 0; kk < 16; kk++) {
            float a[4], b[4];
            #pragma unroll
            for (int i = 0; i < 4; i++) a[i] = As[kk][ty * 4 + i];
            #pragma unroll
            for (int j = 0; j < 4; j++) b[j] = Ws[kk][tx * 4 + j];
            #pragma unroll
            for (int i = 0; i < 4; i++)
                #pragma unroll
                for (int j = 0; j < 4; j++)
                    acc[i][j] += a[i] * b[j];
        }
        __syncthreads();
    }

    #pragma unroll
    for (int i = 0; i < 4; i++) {
        int row = m0 + ty * 4 + i;
        if (row >= M) continue;
        #pragma unroll
        for (int j = 0; j < 4; j++) {
            int col = n0 + tx * 4 + j;
            if (col >= N) continue;
            float r = acc[i][j];
            if (bias) r += bias[col];
            C[(size_t)row * ldc + col] = r;
        }
    }
}

// ---------------------------------------------------------------------------
// Fused score kernel: logits[b,h,q,k] = (q+u)*scale . k  +  (q+v)*scale . pk[k-q+L-1]
// 32x32 output tile per block; diagonal 63-row p_k band in smem.
// ---------------------------------------------------------------------------
__global__ void score_kernel(const float* __restrict__ ub, const float* __restrict__ vbb,
                             float* __restrict__ attn)
{
    const int z  = blockIdx.z;          // b*H + h
    const int b  = z >> 3, h = z & 7;
    const int q0 = blockIdx.y * 32;
    const int k0 = blockIdx.x * 32;
    const float scale = 0.044194173824159216f; // 1/sqrt(512)

    __shared__ float squ[32][65];
    __shared__ float sqv[32][65];
    __shared__ float sk [32][65];
    __shared__ float spk[63][65];

    const int t = threadIdx.x;

    for (int i = t; i < 32 * 64; i += 256) {
        int r = i >> 6, d = i & 63;
        float qv = g_proj[((size_t)(b * Lq + q0 + r)) * QKVq + h * 192 + d];
        squ[r][d] = (qv + ub [h * 64 + d]) * scale;
        sqv[r][d] = (qv + vbb[h * 64 + d]) * scale;
        sk [r][d] =  g_proj[((size_t)(b * Lq + k0 + r)) * QKVq + h * 192 + 64 + d];
    }
    const int p0 = k0 - q0 + 992;   // k0 - q0 + (L-1) - 31; always in [0, P-63]
    for (int i = t; i < 63 * 64; i += 256) {
        int r = i >> 6, d = i & 63;
        spk[r][d] = g_pk[(size_t)(p0 + r) * Eq + h * 64 + d];
    }
    __syncthreads();

    const int tx = t & 15, ty = t >> 4;
    const int qi = ty * 2, kj = tx * 2;
    const int rc = 31 + kj - qi;    // spk row for (qi, kj); in [1, 61]

    float a00 = 0.f, a01 = 0.f, a10 = 0.f, a11 = 0.f;
    #pragma unroll 4
    for (int d = 0; d < 64; d++) {
        float u0 = squ[qi][d],     u1 = squ[qi + 1][d];
        float w0 = sqv[qi][d],     w1 = sqv[qi + 1][d];
        float b0 = sk [kj][d],     b1 = sk [kj + 1][d];
        float pm = spk[rc - 1][d], pc = spk[rc][d], pp = spk[rc + 1][d];
        a00 += u0 * b0 + w0 * pc;
        a01 += u0 * b1 + w0 * pp;
        a10 += u1 * b0 + w1 * pm;
        a11 += u1 * b1 + w1 * pc;
    }

    size_t base = ((size_t)z * Lq + q0 + qi) * Lq + k0 + kj;
    attn[base]            = a00;
    attn[base + 1]        = a01;
    attn[base + Lq]       = a10;
    attn[base + Lq + 1]   = a11;
}

// ---------------------------------------------------------------------------
// Row softmax in-place. One block (256 threads) per row of 1024.
// ---------------------------------------------------------------------------
__global__ void softmax_kernel(float* __restrict__ attn)
{
    float* row = attn + (size_t)blockIdx.x * Lq;
    const int t = threadIdx.x;
    float4 v = *(reinterpret_cast<float4*>(row) + t);

    float m = fmaxf(fmaxf(v.x, v.y), fmaxf(v.z, v.w));
    #pragma unroll
    for (int o = 16; o > 0; o >>= 1) m = fmaxf(m, __shfl_xor_sync(0xffffffffu, m, o));

    __shared__ float red[8];
    if ((t & 31) == 0) red[t >> 5] = m;
    __syncthreads();
    float bm = red[0];
    #pragma unroll
    for (int i = 1; i < 8; i++) bm = fmaxf(bm, red[i]);

    v.x = expf(v.x - bm); v.y = expf(v.y - bm);
    v.z = expf(v.z - bm); v.w = expf(v.w - bm);
    float s = v.x + v.y + v.z + v.w;
    #pragma unroll
    for (int o = 16; o > 0; o >>= 1) s += __shfl_xor_sync(0xffffffffu, s, o);

    __syncthreads();
    if ((t & 31) == 0) red[t >> 5] = s;
    __syncthreads();
    float bs = red[0];
    #pragma unroll
    for (int i = 1; i < 8; i++) bs += red[i];
    float inv = 1.0f / bs;

    v.x *= inv; v.y *= inv; v.z *= inv; v.w *= inv;
    *(reinterpret_cast<float4*>(row) + t) = v;
}

// ---------------------------------------------------------------------------
// ctx[b,q,h,d] = sum_k attn[b,h,q,k] * v[b,k,h,d].  Per (b,h): (1024x1024)@(1024x64).
// 64(q) x 64(d) tile, BK=16.
// ---------------------------------------------------------------------------
__global__ void ctx_gemm(const float* __restrict__ attn)
{
    const int z = blockIdx.z;
    const int b = z >> 3, h = z & 7;
    const float* A  = attn  + (size_t)z * Lq * Lq;                      // lda = 1024
    const float* Bm = g_proj + (size_t)b * Lq * QKVq + h * 192 + 128;   // ldb = 1536
    float*       Cm = g_ctx  + (size_t)b * Lq * Eq + h * 64;            // ldc = 512

    __shared__ float As[16][65];
    __shared__ float Bs[16][65];

    const int m0 = blockIdx.y * 64;
    const int t  = threadIdx.x;
    const int tx = t & 15, ty = t >> 4;

    float acc[4][4] = {};

    for (int k0 = 0; k0 < Lq; k0 += 16) {
        {   // A tile: 64 x 16
            int lr = t >> 2, lc = (t & 3) * 4;
            float4 av = *(const float4*)(A + (size_t)(m0 + lr) * Lq + k0 + lc);
            As[lc + 0][lr] = av.x; As[lc + 1][lr] = av.y;
            As[lc + 2][lr] = av.z; As[lc + 3][lr] = av.w;
        }
        {   // B tile: 16 x 64
            int br = t >> 4, bc = (t & 15) * 4;
            float4 bv = *(const float4*)(Bm + (size_t)(k0 + br) * QKVq + bc);
            Bs[br][bc + 0] = bv.x; Bs[br][bc + 1] = bv.y;
            Bs[br][bc + 2] = bv.z; Bs[br][bc + 3] = bv.w;
        }
        __syncthreads();
        #pragma unroll
        for (int kk = 0; kk < 16; kk++) {
            float a[4], bb[4];
            #pragma unroll
            for (int i = 0; i < 4; i++) a[i]  = As[kk][ty * 4 + i];
            #pragma unroll
            for (int j = 0; j < 4; j++) bb[j] = Bs[kk][tx * 4 + j];
            #pragma unroll
            for (int i = 0; i < 4; i++)
                #pragma unroll
                for (int j = 0; j < 4; j++)
                    acc[i][j] += a[i] * bb[j];
        }
        __syncthreads();
    }

    #pragma unroll
    for (int i = 0; i < 4; i++)
        #pragma unroll
        for (int j = 0; j < 4; j++)
            Cm[(size_t)(m0 + ty * 4 + i) * Eq + tx * 4 + j] = acc[i][j];
}

// ---------------------------------------------------------------------------
extern "C" void kernel_launch(void* const* d_in, const int* in_sizes, int n_in,
                              void* d_out, int out_size)
{
    const float* x     = (const float*)d_in[0];
    const float* pos   = (const float*)d_in[1];
    const float* w_in  = (const float*)d_in[2];
    const float* w_pos = (const float*)d_in[3];
    const float* w_out = (const float*)d_in[4];
    const float* b_out = (const float*)d_in[5];
    const float* ub    = (const float*)d_in[6];
    const float* vbb   = (const float*)d_in[7];
    float* out = (float*)d_out;

    float *proj, *pk, *ctx, *attn_fb;
    cudaGetSymbolAddress((void**)&proj,    g_proj);
    cudaGetSymbolAddress((void**)&pk,      g_pk);
    cudaGetSymbolAddress((void**)&ctx,     g_ctx);
    cudaGetSymbolAddress((void**)&attn_fb, g_attn_fb);

    const size_t OUT_E  = (size_t)BLq * Eq;                 // 4,194,304
    const size_t ATTN_E = (size_t)Bq * Hq * Lq * Lq;        // 67,108,864
    float* attn = ((size_t)out_size >= OUT_E + ATTN_E) ? (out + OUT_E) : attn_fb;

    // 1) QKV projection: (8192,512) @ (1536,512)^T -> (8192,1536)
    gemm_nt<<<dim3(QKVq / 64, BLq / 64), 256>>>(x, w_in, nullptr, proj,
                                                BLq, QKVq, Eq, Eq, Eq, QKVq);
    // 2) positional keys: (2047,512) @ (512,512)^T -> (2047,512)
    gemm_nt<<<dim3(Eq / 64, (Pq + 63) / 64), 256>>>(pos, w_pos, nullptr, pk,
                                                    Pq, Eq, Eq, Eq, Eq, Eq);
    // 3) fused AC + shifted BD logits
    score_kernel<<<dim3(Lq / 32, Lq / 32, Bq * Hq), 256>>>(ub, vbb, attn);
    // 4) row softmax in place
    softmax_kernel<<<Bq * Hq * Lq, 256>>>(attn);
    // 5) ctx = attn @ V
    ctx_gemm<<<dim3(1, Lq / 64, Bq * Hq), 256>>>(attn);
    // 6) out projection + bias
    gemm_nt<<<dim3(Eq / 64, BLq / 64), 256>>>(ctx, w_out, b_out, out,
                                              BLq, Eq, Eq, Eq, Eq, Eq);
}

// round 2
// speedup vs baseline: 1.5241x; 1.5241x over previous
#include <cuda_runtime.h>
#include <cuda_bf16.h>
#include <cstdint>

#define Bq   8
#define Lq   1024
#define Eq   512
#define Hq   8
#define HDq  64
#define Pq   2047
#define BLq  8192
#define QKVq 1536
#define SCALEF 0.044194173824159216f  // 1/sqrt(512)

__device__ float g_proj[(size_t)BLq * QKVq];
__device__ float g_pk[(size_t)Pq * Eq];
__device__ float g_ctx[(size_t)BLq * Eq];
__device__ float g_attn_fb[(size_t)Bq * Hq * Lq * Lq];

// ---------------------------------------------------------------------------
// Generic SGEMM: C[M,N] = A[M,K] @ W[N,K]^T (+bias). 128x128 tile, BK=16,
// 256 threads, 8x8 microtile, float4 smem reads. N must be multiple of 128.
// ---------------------------------------------------------------------------
__global__ void __launch_bounds__(256, 2)
gemm128(const float* __restrict__ A, const float* __restrict__ W,
        const float* __restrict__ bias, float* __restrict__ C,
        int M, int N, int K, int lda, int ldw, int ldc)
{
    __shared__ float As[16][132];
    __shared__ float Ws[16][132];
    const int m0 = blockIdx.y * 128, n0 = blockIdx.x * 128;
    const int t  = threadIdx.x;
    const int tx = t & 15, ty = t >> 4;

    float acc[8][8] = {};

    for (int k0 = 0; k0 < K; k0 += 16) {
        #pragma unroll
        for (int i = 0; i < 2; i++) {
            int idx = t + i * 256;
            int row = idx >> 2, kc = (idx & 3) * 4;
            float4 av = make_float4(0.f,0.f,0.f,0.f);
            if (m0 + row < M) av = *(const float4*)(A + (size_t)(m0+row)*lda + k0 + kc);
            As[kc][row]=av.x; As[kc+1][row]=av.y; As[kc+2][row]=av.z; As[kc+3][row]=av.w;
            float4 wv = make_float4(0.f,0.f,0.f,0.f);
            if (n0 + row < N) wv = *(const float4*)(W + (size_t)(n0+row)*ldw + k0 + kc);
            Ws[kc][row]=wv.x; Ws[kc+1][row]=wv.y; Ws[kc+2][row]=wv.z; Ws[kc+3][row]=wv.w;
        }
        __syncthreads();
        #pragma unroll
        for (int kk = 0; kk < 16; kk++) {
            float a[8], b[8];
            *(float4*)(a)   = *(const float4*)&As[kk][ty*8];
            *(float4*)(a+4) = *(const float4*)&As[kk][ty*8+4];
            *(float4*)(b)   = *(const float4*)&Ws[kk][tx*8];
            *(float4*)(b+4) = *(const float4*)&Ws[kk][tx*8+4];
            #pragma unroll
            for (int i = 0; i < 8; i++)
                #pragma unroll
                for (int j = 0; j < 8; j++)
                    acc[i][j] += a[i] * b[j];
        }
        __syncthreads();
    }

    #pragma unroll
    for (int i = 0; i < 8; i++) {
        int row = m0 + ty*8 + i;
        if (row >= M) continue;
        #pragma unroll
        for (int j = 0; j < 8; j += 4) {
            int col = n0 + tx*8 + j;
            float4 r = make_float4(acc[i][j], acc[i][j+1], acc[i][j+2], acc[i][j+3]);
            if (bias) { r.x += bias[col]; r.y += bias[col+1]; r.z += bias[col+2]; r.w += bias[col+3]; }
            *(float4*)(C + (size_t)row*ldc + col) = r;
        }
    }
}

// ---------------------------------------------------------------------------
// AC: attn[z,q,k] = ((q_vec + u) * scale) . k_vec.  Per z=(b,h): 1024x1024x64.
// ---------------------------------------------------------------------------
__global__ void __launch_bounds__(256, 2)
ac_gemm(const float* __restrict__ ub, float* __restrict__ attn)
{
    const int z = blockIdx.z, b = z >> 3, h = z & 7;
    const float* A  = g_proj + (size_t)b*Lq*QKVq + h*192;        // q-part
    const float* Bk = g_proj + (size_t)b*Lq*QKVq + h*192 + 64;   // k-part
    float* Cc = attn + (size_t)z * Lq * Lq;

    __shared__ float As[16][132];
    __shared__ float Ws[16][132];
    const int m0 = blockIdx.y * 128, n0 = blockIdx.x * 128;
    const int t  = threadIdx.x;
    const int tx = t & 15, ty = t >> 4;

    float acc[8][8] = {};

    for (int k0 = 0; k0 < 64; k0 += 16) {
        #pragma unroll
        for (int i = 0; i < 2; i++) {
            int idx = t + i * 256;
            int row = idx >> 2, kc = (idx & 3) * 4;
            float4 av = *(const float4*)(A + (size_t)(m0+row)*QKVq + k0 + kc);
            const float* up = ub + h*64 + k0 + kc;
            As[kc][row]   = (av.x + up[0]) * SCALEF;
            As[kc+1][row] = (av.y + up[1]) * SCALEF;
            As[kc+2][row] = (av.z + up[2]) * SCALEF;
            As[kc+3][row] = (av.w + up[3]) * SCALEF;
            float4 wv = *(const float4*)(Bk + (size_t)(n0+row)*QKVq + k0 + kc);
            Ws[kc][row]=wv.x; Ws[kc+1][row]=wv.y; Ws[kc+2][row]=wv.z; Ws[kc+3][row]=wv.w;
        }
        __syncthreads();
        #pragma unroll
        for (int kk = 0; kk < 16; kk++) {
            float a[8], bb[8];
            *(float4*)(a)    = *(const float4*)&As[kk][ty*8];
            *(float4*)(a+4)  = *(const float4*)&As[kk][ty*8+4];
            *(float4*)(bb)   = *(const float4*)&Ws[kk][tx*8];
            *(float4*)(bb+4) = *(const float4*)&Ws[kk][tx*8+4];
            #pragma unroll
            for (int i = 0; i < 8; i++)
                #pragma unroll
                for (int j = 0; j < 8; j++)
                    acc[i][j] += a[i] * bb[j];
        }
        __syncthreads();
    }

    #pragma unroll
    for (int i = 0; i < 8; i++) {
        int row = m0 + ty*8 + i;
        #pragma unroll
        for (int j = 0; j < 8; j += 4)
            *(float4*)(Cc + (size_t)row*Lq + n0 + tx*8 + j) =
                make_float4(acc[i][j], acc[i][j+1], acc[i][j+2], acc[i][j+3]);
    }
}

// ---------------------------------------------------------------------------
// BD in (q, j) space: bd[q,j] = ((q_vec + v) * scale) . pk[j]; scatter-add
// attn[z, q, q + j - 1023] for k in [0,1024). j-tiles cover the needed band.
// ---------------------------------------------------------------------------
__global__ void __launch_bounds__(256, 2)
bd_gemm(const float* __restrict__ vbb, float* __restrict__ attn)
{
    const int z = blockIdx.z, b = z >> 3, h = z & 7;
    const int q0 = blockIdx.y * 128;
    const int j0 = 896 - q0 + blockIdx.x * 128;   // in [0, 1920]
    const float* A = g_proj + (size_t)b*Lq*QKVq + h*192;   // q-part
    const float* P = g_pk + h*64;                          // row stride Eq
    float* Cc = attn + (size_t)z * Lq * Lq;

    __shared__ float As[16][132];
    __shared__ float Ws[16][132];
    const int t  = threadIdx.x;
    const int tx = t & 15, ty = t >> 4;

    float acc[8][8] = {};

    for (int k0 = 0; k0 < 64; k0 += 16) {
        #pragma unroll
        for (int i = 0; i < 2; i++) {
            int idx = t + i * 256;
            int row = idx >> 2, kc = (idx & 3) * 4;
            float4 av = *(const float4*)(A + (size_t)(q0+row)*QKVq + k0 + kc);
            const float* vp = vbb + h*64 + k0 + kc;
            As[kc][row]   = (av.x + vp[0]) * SCALEF;
            As[kc+1][row] = (av.y + vp[1]) * SCALEF;
            As[kc+2][row] = (av.z + vp[2]) * SCALEF;
            As[kc+3][row] = (av.w + vp[3]) * SCALEF;
            float4 wv = make_float4(0.f,0.f,0.f,0.f);
            if (j0 + row < Pq) wv = *(const float4*)(P + (size_t)(j0+row)*Eq + k0 + kc);
            Ws[kc][row]=wv.x; Ws[kc+1][row]=wv.y; Ws[kc+2][row]=wv.z; Ws[kc+3][row]=wv.w;
        }
        __syncthreads();
        #pragma unroll
        for (int kk = 0; kk < 16; kk++) {
            float a[8], bb[8];
            *(float4*)(a)    = *(const float4*)&As[kk][ty*8];
            *(float4*)(a+4)  = *(const float4*)&As[kk][ty*8+4];
            *(float4*)(bb)   = *(const float4*)&Ws[kk][tx*8];
            *(float4*)(bb+4) = *(const float4*)&Ws[kk][tx*8+4];
            #pragma unroll
            for (int i = 0; i < 8; i++)
                #pragma unroll
                for (int j = 0; j < 8; j++)
                    acc[i][j] += a[i] * bb[j];
        }
        __syncthreads();
    }

    #pragma unroll
    for (int i = 0; i < 8; i++) {
        int q = q0 + ty*8 + i;
        int kb = q + j0 + tx*8 - 1023;         // k for jj=0
        float* rowp = Cc + (size_t)q * Lq;
        #pragma unroll
        for (int jj = 0; jj < 8; jj++) {
            int k = kb + jj;
            if (k >= 0 && k < Lq) rowp[k] += acc[i][jj];
        }
    }
}

// ---------------------------------------------------------------------------
// Row softmax in-place (1024 per row, 256 threads/row).
// ---------------------------------------------------------------------------
__global__ void softmax_kernel(float* __restrict__ attn)
{
    float* row = attn + (size_t)blockIdx.x * Lq;
    const int t = threadIdx.x;
    float4 v = *(reinterpret_cast<float4*>(row) + t);

    float m = fmaxf(fmaxf(v.x, v.y), fmaxf(v.z, v.w));
    #pragma unroll
    for (int o = 16; o > 0; o >>= 1) m = fmaxf(m, __shfl_xor_sync(0xffffffffu, m, o));
    __shared__ float red[8];
    if ((t & 31) == 0) red[t >> 5] = m;
    __syncthreads();
    float bm = red[0];
    #pragma unroll
    for (int i = 1; i < 8; i++) bm = fmaxf(bm, red[i]);

    v.x = expf(v.x - bm); v.y = expf(v.y - bm);
    v.z = expf(v.z - bm); v.w = expf(v.w - bm);
    float s = v.x + v.y + v.z + v.w;
    #pragma unroll
    for (int o = 16; o > 0; o >>= 1) s += __shfl_xor_sync(0xffffffffu, s, o);
    __syncthreads();
    if ((t & 31) == 0) red[t >> 5] = s;
    __syncthreads();
    float bs = red[0];
    #pragma unroll
    for (int i = 1; i < 8; i++) bs += red[i];
    float inv = 1.0f / bs;
    v.x *= inv; v.y *= inv; v.z *= inv; v.w *= inv;
    *(reinterpret_cast<float4*>(row) + t) = v;
}

// ---------------------------------------------------------------------------
// ctx[b,q,h,:] = attn[z] @ V[z].  Per z: 1024x64x1024. Tile 128(M)x64(N),
// BK=16, 256 threads, 8x4 microtile.
// ---------------------------------------------------------------------------
__global__ void __launch_bounds__(256, 2)
ctx_gemm(const float* __restrict__ attn)
{
    const int z = blockIdx.z, b = z >> 3, h = z & 7;
    const float* A  = attn  + (size_t)z * Lq * Lq;
    const float* Vm = g_proj + (size_t)b*Lq*QKVq + h*192 + 128;
    float*       Cm = g_ctx  + (size_t)b*Lq*Eq + h*64;

    __shared__ float As[16][132];
    __shared__ float Bs[16][68];
    const int m0 = blockIdx.y * 128;
    const int t  = threadIdx.x;
    const int tx = t & 15, ty = t >> 4;

    float acc[8][4] = {};

    for (int k0 = 0; k0 < Lq; k0 += 16) {
        #pragma unroll
        for (int i = 0; i < 2; i++) {
            int idx = t + i * 256;
            int row = idx >> 2, kc = (idx & 3) * 4;
            float4 av = *(const float4*)(A + (size_t)(m0+row)*Lq + k0 + kc);
            As[kc][row]=av.x; As[kc+1][row]=av.y; As[kc+2][row]=av.z; As[kc+3][row]=av.w;
        }
        {
            int row = t >> 4, c4 = (t & 15) * 4;
            float4 bv = *(const float4*)(Vm + (size_t)(k0+row)*QKVq + c4);
            *(float4*)&Bs[row][c4] = bv;
        }
        __syncthreads();
        #pragma unroll
        for (int kk = 0; kk < 16; kk++) {
            float a[8], bb[4];
            *(float4*)(a)   = *(const float4*)&As[kk][ty*8];
            *(float4*)(a+4) = *(const float4*)&As[kk][ty*8+4];
            *(float4*)(bb)  = *(const float4*)&Bs[kk][tx*4];
            #pragma unroll
            for (int i = 0; i < 8; i++)
                #pragma unroll
                for (int j = 0; j < 4; j++)
                    acc[i][j] += a[i] * bb[j];
        }
        __syncthreads();
    }

    #pragma unroll
    for (int i = 0; i < 8; i++)
        *(float4*)(Cm + (size_t)(m0 + ty*8 + i)*Eq + tx*4) =
            make_float4(acc[i][0], acc[i][1], acc[i][2], acc[i][3]);
}

// ---------------------------------------------------------------------------
extern "C" void kernel_launch(void* const* d_in, const int* in_sizes, int n_in,
                              void* d_out, int out_size)
{
    const float* x     = (const float*)d_in[0];
    const float* pos   = (const float*)d_in[1];
    const float* w_in  = (const float*)d_in[2];
    const float* w_pos = (const float*)d_in[3];
    const float* w_out = (const float*)d_in[4];
    const float* b_out = (const float*)d_in[5];
    const float* ub    = (const float*)d_in[6];
    const float* vbb   = (const float*)d_in[7];
    float* out = (float*)d_out;

    float *proj, *pk, *ctx, *attn_fb;
    cudaGetSymbolAddress((void**)&proj,    g_proj);
    cudaGetSymbolAddress((void**)&pk,      g_pk);
    cudaGetSymbolAddress((void**)&ctx,     g_ctx);
    cudaGetSymbolAddress((void**)&attn_fb, g_attn_fb);

    const size_t OUT_E  = (size_t)BLq * Eq;
    const size_t ATTN_E = (size_t)Bq * Hq * Lq * Lq;
    float* attn = ((size_t)out_size >= OUT_E + ATTN_E) ? (out + OUT_E) : attn_fb;

    // 1) QKV projection (8192,1536,512)
    gemm128<<<dim3(QKVq/128, BLq/128), 256>>>(x, w_in, nullptr, proj,
                                              BLq, QKVq, Eq, Eq, Eq, QKVq);
    // 2) positional keys (2047,512,512)
    gemm128<<<dim3(Eq/128, (Pq+127)/128), 256>>>(pos, w_pos, nullptr, pk,
                                                 Pq, Eq, Eq, Eq, Eq, Eq);
    // 3) AC logits
    ac_gemm<<<dim3(Lq/128, Lq/128, Bq*Hq), 256>>>(ub, attn);
    // 4) BD logits, shifted scatter-add (stream-ordered after AC)
    bd_gemm<<<dim3(9, Lq/128, Bq*Hq), 256>>>(vbb, attn);
    // 5) softmax
    softmax_kernel<<<Bq*Hq*Lq, 256>>>(attn);
    // 6) ctx = attn @ V
    ctx_gemm<<<dim3(1, Lq/128, Bq*Hq), 256>>>(attn);
    // 7) out projection + bias
    gemm128<<<dim3(Eq/128, BLq/128), 256>>>(ctx, w_out, b_out, out,
                                            BLq, Eq, Eq, Eq, Eq, Eq);
}

// round 4
// speedup vs baseline: 1.6784x; 1.1012x over previous
#include <cuda_runtime.h>
#include <cuda_bf16.h>
#include <cstdint>

#define Bq   8
#define Lq   1024
#define Eq   512
#define Hq   8
#define HDq  64
#define Pq   2047
#define BLq  8192
#define QKVq 1536
#define SCALEF 0.044194173824159216f  // 1/sqrt(512)

__device__ float g_proj[(size_t)BLq * QKVq];
__device__ float g_pk[(size_t)Pq * Eq];
__device__ float g_ctx[(size_t)BLq * Eq];
__device__ float g_attn_fb[(size_t)Bq * Hq * Lq * Lq];

// ---------------------------------------------------------------------------
// Generic SGEMM: C[M,N] = A[M,K] @ W[N,K]^T (+bias). 128x128 tile, BK=16,
// 256 threads, 8x8 microtile.
// ---------------------------------------------------------------------------
__global__ void __launch_bounds__(256, 2)
gemm128(const float* __restrict__ A, const float* __restrict__ W,
        const float* __restrict__ bias, float* __restrict__ C,
        int M, int N, int K, int lda, int ldw, int ldc)
{
    __shared__ float As[16][132];
    __shared__ float Ws[16][132];
    const int m0 = blockIdx.y * 128, n0 = blockIdx.x * 128;
    const int t  = threadIdx.x;
    const int tx = t & 15, ty = t >> 4;

    float acc[8][8] = {};

    for (int k0 = 0; k0 < K; k0 += 16) {
        #pragma unroll
        for (int i = 0; i < 2; i++) {
            int idx = t + i * 256;
            int row = idx >> 2, kc = (idx & 3) * 4;
            float4 av = make_float4(0.f,0.f,0.f,0.f);
            if (m0 + row < M) av = *(const float4*)(A + (size_t)(m0+row)*lda + k0 + kc);
            As[kc][row]=av.x; As[kc+1][row]=av.y; As[kc+2][row]=av.z; As[kc+3][row]=av.w;
            float4 wv = make_float4(0.f,0.f,0.f,0.f);
            if (n0 + row < N) wv = *(const float4*)(W + (size_t)(n0+row)*ldw + k0 + kc);
            Ws[kc][row]=wv.x; Ws[kc+1][row]=wv.y; Ws[kc+2][row]=wv.z; Ws[kc+3][row]=wv.w;
        }
        __syncthreads();
        #pragma unroll
        for (int kk = 0; kk < 16; kk++) {
            float a[8], b[8];
            *(float4*)(a)   = *(const float4*)&As[kk][ty*8];
            *(float4*)(a+4) = *(const float4*)&As[kk][ty*8+4];
            *(float4*)(b)   = *(const float4*)&Ws[kk][tx*8];
            *(float4*)(b+4) = *(const float4*)&Ws[kk][tx*8+4];
            #pragma unroll
            for (int i = 0; i < 8; i++)
                #pragma unroll
                for (int j = 0; j < 8; j++)
                    acc[i][j] += a[i] * b[j];
        }
        __syncthreads();
    }

    #pragma unroll
    for (int i = 0; i < 8; i++) {
        int row = m0 + ty*8 + i;
        if (row >= M) continue;
        #pragma unroll
        for (int j = 0; j < 8; j += 4) {
            int col = n0 + tx*8 + j;
            float4 r = make_float4(acc[i][j], acc[i][j+1], acc[i][j+2], acc[i][j+3]);
            if (bias) { r.x += bias[col]; r.y += bias[col+1]; r.z += bias[col+2]; r.w += bias[col+3]; }
            *(float4*)(C + (size_t)row*ldc + col) = r;
        }
    }
}

// ---------------------------------------------------------------------------
// Fused score kernel, one plain store per attn element:
//   attn[z,q,k] = (Qu[q] . K[k]) + (Qv[q] . pk[k - q + 1023])
// 128x128 tile; the needed pk rows form a 255-row band, always in range.
// Sp rows padded to 260 floats so every row base is 16B-aligned.
// ---------------------------------------------------------------------------
__global__ void __launch_bounds__(256, 2)
score_fused(const float* __restrict__ ub, const float* __restrict__ vbb,
            float* __restrict__ attn)
{
    const int z = blockIdx.z, b = z >> 3, h = z & 7;
    const int q0 = blockIdx.y * 128, k0 = blockIdx.x * 128;
    const float* Aq = g_proj + (size_t)b*Lq*QKVq + h*192;        // q-part
    const float* Bk = g_proj + (size_t)b*Lq*QKVq + h*192 + 64;   // k-part
    const float* Pk = g_pk + h*64;                               // row stride Eq
    float* Cc = attn + (size_t)z * Lq * Lq;

    const int j0 = k0 - q0 + 896;  // band start, in [0, 1792]; rows j0..j0+254

    __shared__ float Su[16][132];
    __shared__ float Sv[16][132];
    __shared__ float Sk[16][132];
    __shared__ float Sp[16][260];   // 255 used; stride 260 => 16B-aligned rows

    const int t  = threadIdx.x;
    const int tx = t & 15, ty = t >> 4;
    const int r0 = tx*8 - ty*8 + 127;   // band row for (i=0, j=0), in [7, 247]

    float acc[8][8] = {};

    for (int d0 = 0; d0 < 64; d0 += 16) {
        // Q (two flavors) + K tiles: 128 rows x 16 dims
        #pragma unroll
        for (int i = 0; i < 2; i++) {
            int idx = t + i * 256;
            int row = idx >> 2, kc = (idx & 3) * 4;
            float4 av = *(const float4*)(Aq + (size_t)(q0+row)*QKVq + d0 + kc);
            const float* up = ub  + h*64 + d0 + kc;
            const float* vp = vbb + h*64 + d0 + kc;
            Su[kc][row]   = (av.x + up[0]) * SCALEF;
            Su[kc+1][row] = (av.y + up[1]) * SCALEF;
            Su[kc+2][row] = (av.z + up[2]) * SCALEF;
            Su[kc+3][row] = (av.w + up[3]) * SCALEF;
            Sv[kc][row]   = (av.x + vp[0]) * SCALEF;
            Sv[kc+1][row] = (av.y + vp[1]) * SCALEF;
            Sv[kc+2][row] = (av.z + vp[2]) * SCALEF;
            Sv[kc+3][row] = (av.w + vp[3]) * SCALEF;
            float4 wv = *(const float4*)(Bk + (size_t)(k0+row)*QKVq + d0 + kc);
            Sk[kc][row]=wv.x; Sk[kc+1][row]=wv.y; Sk[kc+2][row]=wv.z; Sk[kc+3][row]=wv.w;
        }
        // pk band: 255 rows x 16 dims; thread t handles band row t
        if (t < 255) {
            const float* pr = Pk + (size_t)(j0 + t) * Eq + d0;
            #pragma unroll
            for (int c = 0; c < 16; c += 4) {
                float4 pv = *(const float4*)(pr + c);
                Sp[c][t] = pv.x; Sp[c+1][t] = pv.y; Sp[c+2][t] = pv.z; Sp[c+3][t] = pv.w;
            }
        }
        __syncthreads();

        #pragma unroll
        for (int kk = 0; kk < 16; kk++) {
            float au[8], av_[8], bk[8], p[16];
            *(float4*)(au)    = *(const float4*)&Su[kk][ty*8];
            *(float4*)(au+4)  = *(const float4*)&Su[kk][ty*8+4];
            *(float4*)(av_)   = *(const float4*)&Sv[kk][ty*8];
            *(float4*)(av_+4) = *(const float4*)&Sv[kk][ty*8+4];
            *(float4*)(bk)    = *(const float4*)&Sk[kk][tx*8];
            *(float4*)(bk+4)  = *(const float4*)&Sk[kk][tx*8+4];
            // band slice [r0-7, r0+8]; r0-7 is a multiple of 8 and rows are
            // 16B-aligned (stride 260), so these float4 loads are aligned.
            *(float4*)(p)     = *(const float4*)&Sp[kk][r0-7];
            *(float4*)(p+4)   = *(const float4*)&Sp[kk][r0-3];
            *(float4*)(p+8)   = *(const float4*)&Sp[kk][r0+1];
            *(float4*)(p+12)  = *(const float4*)&Sp[kk][r0+5];
            #pragma unroll
            for (int i = 0; i < 8; i++)
                #pragma unroll
                for (int j = 0; j < 8; j++)
                    acc[i][j] += au[i] * bk[j] + av_[i] * p[7 + j - i];
        }
        __syncthreads();
    }

    #pragma unroll
    for (int i = 0; i < 8; i++) {
        float* rowp = Cc + (size_t)(q0 + ty*8 + i) * Lq + k0 + tx*8;
        #pragma unroll
        for (int j = 0; j < 8; j += 4)
            *(float4*)(rowp + j) = make_float4(acc[i][j], acc[i][j+1],
                                               acc[i][j+2], acc[i][j+3]);
    }
}

// ---------------------------------------------------------------------------
// Row softmax in-place (1024 per row, 256 threads/row).
// ---------------------------------------------------------------------------
__global__ void softmax_kernel(float* __restrict__ attn)
{
    float* row = attn + (size_t)blockIdx.x * Lq;
    const int t = threadIdx.x;
    float4 v = *(reinterpret_cast<float4*>(row) + t);

    float m = fmaxf(fmaxf(v.x, v.y), fmaxf(v.z, v.w));
    #pragma unroll
    for (int o = 16; o > 0; o >>= 1) m = fmaxf(m, __shfl_xor_sync(0xffffffffu, m, o));
    __shared__ float red[8];
    if ((t & 31) == 0) red[t >> 5] = m;
    __syncthreads();
    float bm = red[0];
    #pragma unroll
    for (int i = 1; i < 8; i++) bm = fmaxf(bm, red[i]);

    v.x = expf(v.x - bm); v.y = expf(v.y - bm);
    v.z = expf(v.z - bm); v.w = expf(v.w - bm);
    float s = v.x + v.y + v.z + v.w;
    #pragma unroll
    for (int o = 16; o > 0; o >>= 1) s += __shfl_xor_sync(0xffffffffu, s, o);
    __syncthreads();
    if ((t & 31) == 0) red[t >> 5] = s;
    __syncthreads();
    float bs = red[0];
    #pragma unroll
    for (int i = 1; i < 8; i++) bs += red[i];
    float inv = 1.0f / bs;
    v.x *= inv; v.y *= inv; v.z *= inv; v.w *= inv;
    *(reinterpret_cast<float4*>(row) + t) = v;
}

// ---------------------------------------------------------------------------
// ctx[b,q,h,:] = attn[z] @ V[z].  Per z: 1024x64x1024.
// ---------------------------------------------------------------------------
__global__ void __launch_bounds__(256, 2)
ctx_gemm(const float* __restrict__ attn)
{
    const int z = blockIdx.z, b = z >> 3, h = z & 7;
    const float* A  = attn  + (size_t)z * Lq * Lq;
    const float* Vm = g_proj + (size_t)b*Lq*QKVq + h*192 + 128;
    float*       Cm = g_ctx  + (size_t)b*Lq*Eq + h*64;

    __shared__ float As[16][132];
    __shared__ float Bs[16][68];
    const int m0 = blockIdx.y * 128;
    const int t  = threadIdx.x;
    const int tx = t & 15, ty = t >> 4;

    float acc[8][4] = {};

    for (int k0 = 0; k0 < Lq; k0 += 16) {
        #pragma unroll
        for (int i = 0; i < 2; i++) {
            int idx = t + i * 256;
            int row = idx >> 2, kc = (idx & 3) * 4;
            float4 av = *(const float4*)(A + (size_t)(m0+row)*Lq + k0 + kc);
            As[kc][row]=av.x; As[kc+1][row]=av.y; As[kc+2][row]=av.z; As[kc+3][row]=av.w;
        }
        {
            int row = t >> 4, c4 = (t & 15) * 4;
            float4 bv = *(const float4*)(Vm + (size_t)(k0+row)*QKVq + c4);
            *(float4*)&Bs[row][c4] = bv;
        }
        __syncthreads();
        #pragma unroll
        for (int kk = 0; kk < 16; kk++) {
            float a[8], bb[4];
            *(float4*)(a)   = *(const float4*)&As[kk][ty*8];
            *(float4*)(a+4) = *(const float4*)&As[kk][ty*8+4];
            *(float4*)(bb)  = *(const float4*)&Bs[kk][tx*4];
            #pragma unroll
            for (int i = 0; i < 8; i++)
                #pragma unroll
                for (int j = 0; j < 4; j++)
                    acc[i][j] += a[i] * bb[j];
        }
        __syncthreads();
    }

    #pragma unroll
    for (int i = 0; i < 8; i++)
        *(float4*)(Cm + (size_t)(m0 + ty*8 + i)*Eq + tx*4) =
            make_float4(acc[i][0], acc[i][1], acc[i][2], acc[i][3]);
}

// ---------------------------------------------------------------------------
extern "C" void kernel_launch(void* const* d_in, const int* in_sizes, int n_in,
                              void* d_out, int out_size)
{
    const float* x     = (const float*)d_in[0];
    const float* pos   = (const float*)d_in[1];
    const float* w_in  = (const float*)d_in[2];
    const float* w_pos = (const float*)d_in[3];
    const float* w_out = (const float*)d_in[4];
    const float* b_out = (const float*)d_in[5];
    const float* ub    = (const float*)d_in[6];
    const float* vbb   = (const float*)d_in[7];
    float* out = (float*)d_out;

    float *proj, *pk, *ctx, *attn_fb;
    cudaGetSymbolAddress((void**)&proj,    g_proj);
    cudaGetSymbolAddress((void**)&pk,      g_pk);
    cudaGetSymbolAddress((void**)&ctx,     g_ctx);
    cudaGetSymbolAddress((void**)&attn_fb, g_attn_fb);

    const size_t OUT_E  = (size_t)BLq * Eq;
    const size_t ATTN_E = (size_t)Bq * Hq * Lq * Lq;
    float* attn = ((size_t)out_size >= OUT_E + ATTN_E) ? (out + OUT_E) : attn_fb;

    // 1) QKV projection (8192,1536,512)
    gemm128<<<dim3(QKVq/128, BLq/128), 256>>>(x, w_in, nullptr, proj,
                                              BLq, QKVq, Eq, Eq, Eq, QKVq);
    // 2) positional keys (2047,512,512)
    gemm128<<<dim3(Eq/128, (Pq+127)/128), 256>>>(pos, w_pos, nullptr, pk,
                                                 Pq, Eq, Eq, Eq, Eq, Eq);
    // 3) fused AC + shifted BD logits, single store
    score_fused<<<dim3(Lq/128, Lq/128, Bq*Hq), 256>>>(ub, vbb, attn);
    // 4) softmax
    softmax_kernel<<<Bq*Hq*Lq, 256>>>(attn);
    // 5) ctx = attn @ V
    ctx_gemm<<<dim3(1, Lq/128, Bq*Hq), 256>>>(attn);
    // 6) out projection + bias
    gemm128<<<dim3(Eq/128, BLq/128), 256>>>(ctx, w_out, b_out, out,
                                            BLq, Eq, Eq, Eq, Eq, Eq);
}